// round 1
// baseline (speedup 1.0000x reference)
#include <cuda_runtime.h>
#include <math.h>

#define HN 8      // heads
#define TN 2      // edge types
#define HT 16     // HN*TN
#define NB 16     // batch
#define EN 512    // entities
#define IND 1024  // in_dim
#define ON 128    // per-head dim
#define O2 256    // 2*ON
#define NEGV (-9.0e15f)

// ---------------- device scratch (no allocs allowed) ----------------
__device__ float g_h[(size_t)HT * NB * EN * ON];        // 67 MB: h[ht][n][e][o]
__device__ float g_gv1[HT * NB * ON];                   // g1 * a_src
__device__ float g_gv2[HT * NB * ON];                   // g2 * a_dst
__device__ float g_s1[HT * NB * EN];
__device__ float g_s2[HT * NB * EN];
__device__ float g_coefs[(size_t)HN * NB * EN * EN];    // 134 MB

// ====================================================================
// Kernel A: h[ht][row][o] = sum_d X[row][d] * W[ht][d][o]
//   X: (8192, 1024) row-major, W: (HT, 1024, 128)
//   grid (64, 1, 16), block 256; 128x128x16 tiles, 8x8 per thread
// ====================================================================
__global__ __launch_bounds__(256) void gemm_h_kernel(
    const float* __restrict__ X, const float* __restrict__ W)
{
    __shared__ float As[16][132];   // [k][m], padded
    __shared__ float Bs[16][128];   // [k][o]

    const int ht = blockIdx.z;
    const int m0 = blockIdx.x * 128;
    const float* Wp = W + (size_t)ht * IND * ON;
    const int tid = threadIdx.x;
    const int tx = tid & 15, ty = tid >> 4;

    float acc[8][8];
#pragma unroll
    for (int i = 0; i < 8; i++)
#pragma unroll
        for (int j = 0; j < 8; j++) acc[i][j] = 0.f;

    for (int k0 = 0; k0 < IND; k0 += 16) {
        // X tile: 128 rows x 16 k = 512 float4, 2 per thread; transpose to As[k][m]
#pragma unroll
        for (int l = 0; l < 2; l++) {
            int idx = tid * 2 + l;
            int r = idx >> 2;      // 0..127  (row within tile)
            int c4 = idx & 3;      // which float4 of the 16 k's
            float4 v = *(const float4*)(X + (size_t)(m0 + r) * IND + k0 + c4 * 4);
            As[c4 * 4 + 0][r] = v.x;
            As[c4 * 4 + 1][r] = v.y;
            As[c4 * 4 + 2][r] = v.z;
            As[c4 * 4 + 3][r] = v.w;
        }
        // W tile: 16 k x 128 o = 512 float4, 2 per thread, direct
#pragma unroll
        for (int l = 0; l < 2; l++) {
            int idx = tid * 2 + l;
            int k = idx >> 5;
            int c4 = idx & 31;
            *(float4*)&Bs[k][c4 * 4] =
                *(const float4*)(Wp + (size_t)(k0 + k) * ON + c4 * 4);
        }
        __syncthreads();
#pragma unroll
        for (int k = 0; k < 16; k++) {
            float a[8], b[8];
#pragma unroll
            for (int i = 0; i < 8; i++) a[i] = As[k][ty * 8 + i];
#pragma unroll
            for (int j = 0; j < 8; j++) b[j] = Bs[k][tx * 8 + j];
#pragma unroll
            for (int i = 0; i < 8; i++)
#pragma unroll
                for (int j = 0; j < 8; j++) acc[i][j] = fmaf(a[i], b[j], acc[i][j]);
        }
        __syncthreads();
    }

    float* Cp = g_h + (size_t)ht * NB * EN * ON;
#pragma unroll
    for (int i = 0; i < 8; i++) {
        int m = m0 + ty * 8 + i;
#pragma unroll
        for (int j4 = 0; j4 < 2; j4++) {
            float4 v = make_float4(acc[i][j4 * 4 + 0], acc[i][j4 * 4 + 1],
                                   acc[i][j4 * 4 + 2], acc[i][j4 * 4 + 3]);
            *(float4*)(Cp + (size_t)m * ON + tx * 8 + j4 * 4) = v;
        }
    }
}

// ====================================================================
// Kernel B: query-gate MLP.  grid 16 (ht), block 256.
//   c1 = relu(qv @ qW1[ht])    (16 x 256, K=1024)
//   g  = sigmoid(c1 @ qW2[ht]) (16 x 256, K=256)
//   gv1[ht][n][o] = g[n][o]     * a_src[ht][o]
//   gv2[ht][n][o] = g[n][O+o]   * a_dst[ht][o]
// ====================================================================
__global__ __launch_bounds__(256) void qgate_kernel(
    const float* __restrict__ qv, const float* __restrict__ qW1,
    const float* __restrict__ qW2, const float* __restrict__ a_src,
    const float* __restrict__ a_dst)
{
    __shared__ float qvs[NB][64];
    __shared__ float c1s[NB][O2];

    const int ht = blockIdx.x;
    const int t = threadIdx.x;   // 0..255, one output column each

    float acc[NB];
#pragma unroll
    for (int n = 0; n < NB; n++) acc[n] = 0.f;

    const float* W1 = qW1 + (size_t)ht * IND * O2;
    for (int q0 = 0; q0 < IND; q0 += 64) {
        {   // stage qv chunk: 16 x 64 = 256 float4, 1 per thread
            int n = t >> 4, c4 = t & 15;
            *(float4*)&qvs[n][c4 * 4] =
                *(const float4*)(qv + (size_t)n * IND + q0 + c4 * 4);
        }
        __syncthreads();
#pragma unroll 4
        for (int q = 0; q < 64; q++) {
            float w = W1[(size_t)(q0 + q) * O2 + t];
#pragma unroll
            for (int n = 0; n < NB; n++) acc[n] = fmaf(qvs[n][q], w, acc[n]);
        }
        __syncthreads();
    }
#pragma unroll
    for (int n = 0; n < NB; n++) c1s[n][t] = fmaxf(acc[n], 0.f);
    __syncthreads();

    float acc2[NB];
#pragma unroll
    for (int n = 0; n < NB; n++) acc2[n] = 0.f;
    const float* W2 = qW2 + (size_t)ht * O2 * O2;
    for (int c = 0; c < O2; c++) {
        float w = W2[(size_t)c * O2 + t];
#pragma unroll
        for (int n = 0; n < NB; n++) acc2[n] = fmaf(c1s[n][c], w, acc2[n]);
    }

    if (t < ON) {
        float av = a_src[ht * ON + t];
#pragma unroll
        for (int n = 0; n < NB; n++) {
            float sg = 1.f / (1.f + expf(-acc2[n]));
            g_gv1[((size_t)ht * NB + n) * ON + t] = sg * av;
        }
    } else {
        int o = t - ON;
        float av = a_dst[ht * ON + o];
#pragma unroll
        for (int n = 0; n < NB; n++) {
            float sg = 1.f / (1.f + expf(-acc2[n]));
            g_gv2[((size_t)ht * NB + n) * ON + o] = sg * av;
        }
    }
}

// ====================================================================
// Kernel C: s1[ht][n][e] = <h[ht][n][e][:], gv1[ht][n][:]>, same for s2
//   grid (EN/8, NB, HT), block 256 (8 warps, 1 e-row per warp)
// ====================================================================
__global__ __launch_bounds__(256) void svec_kernel()
{
    const int ht = blockIdx.z, n = blockIdx.y;
    const int warp = threadIdx.x >> 5, lane = threadIdx.x & 31;
    const int e = blockIdx.x * 8 + warp;

    const float* hp = g_h + (((size_t)ht * NB + n) * EN + e) * ON;
    const float* v1 = g_gv1 + ((size_t)ht * NB + n) * ON;
    const float* v2 = g_gv2 + ((size_t)ht * NB + n) * ON;

    float a1 = 0.f, a2 = 0.f;
#pragma unroll
    for (int r = 0; r < 4; r++) {
        float hv = hp[lane + r * 32];
        a1 = fmaf(hv, v1[lane + r * 32], a1);
        a2 = fmaf(hv, v2[lane + r * 32], a2);
    }
#pragma unroll
    for (int off = 16; off > 0; off >>= 1) {
        a1 += __shfl_xor_sync(0xffffffffu, a1, off);
        a2 += __shfl_xor_sync(0xffffffffu, a2, off);
    }
    if (lane == 0) {
        g_s1[((size_t)ht * NB + n) * EN + e] = a1;
        g_s2[((size_t)ht * NB + n) * EN + e] = a2;
    }
}

// ====================================================================
// Kernel D: per row (h,n,i): scores over j, masked by adj, softmax,
//           write coefs.  grid (EN, NB, HN), block 128 (4 j per thread)
// ====================================================================
__global__ __launch_bounds__(128) void softmax_kernel(const int* __restrict__ adj)
{
    const int i = blockIdx.x, n = blockIdx.y, h = blockIdx.z;
    const int t = threadIdx.x;
    const int warp = t >> 5, lane = t & 31;

    __shared__ float s2row[2][EN];
    __shared__ float red[8];

    for (int tt = 0; tt < 2; tt++)
        for (int j = t; j < EN; j += 128)
            s2row[tt][j] = g_s2[(((size_t)(h * 2 + tt) * NB) + n) * EN + j];

    float s1v0 = g_s1[(((size_t)(h * 2 + 0) * NB) + n) * EN + i];
    float s1v1 = g_s1[(((size_t)(h * 2 + 1) * NB) + n) * EN + i];
    __syncthreads();

    const int* arow = adj + ((size_t)n * EN + i) * EN;
    float v[4];
    float mx = NEGV;
#pragma unroll
    for (int r = 0; r < 4; r++) {
        int j = t + r * 128;
        int a = arow[j];
        float val;
        if (a > 0) {
            float x = (a == 1 ? s1v0 + s2row[0][j] : s1v1 + s2row[1][j]);
            val = x > 0.f ? x : 0.2f * x;
        } else {
            val = NEGV;
        }
        v[r] = val;
        mx = fmaxf(mx, val);
    }
    // block max
#pragma unroll
    for (int off = 16; off > 0; off >>= 1)
        mx = fmaxf(mx, __shfl_xor_sync(0xffffffffu, mx, off));
    if (lane == 0) red[warp] = mx;
    __syncthreads();
    mx = fmaxf(fmaxf(red[0], red[1]), fmaxf(red[2], red[3]));

    float sum = 0.f;
#pragma unroll
    for (int r = 0; r < 4; r++) {
        v[r] = expf(v[r] - mx);
        sum += v[r];
    }
#pragma unroll
    for (int off = 16; off > 0; off >>= 1)
        sum += __shfl_xor_sync(0xffffffffu, sum, off);
    if (lane == 0) red[4 + warp] = sum;
    __syncthreads();
    sum = red[4] + red[5] + red[6] + red[7];

    float inv = 1.f / sum;
    float* crow = g_coefs + ((((size_t)h * NB + n) * EN) + i) * EN;
#pragma unroll
    for (int r = 0; r < 4; r++) crow[t + r * 128] = v[r] * inv;
}

// ====================================================================
// Kernel E: per (h,n): Cout[j][o] = sum_i coefs[i][j] * h_last[i][o]
//   then out[n][j][h*128+o] = relu(Cout)
//   grid (EN/128=4, 1, HN*NB=128), block 256; both operands k-major
// ====================================================================
__global__ __launch_bounds__(256) void gemm_out_kernel(float* __restrict__ out)
{
    __shared__ float As[16][128];   // coefs[k=i][j]
    __shared__ float Bs[16][128];   // h_last[k=i][o]

    const int hn = blockIdx.z;
    const int h = hn / NB, n = hn % NB;
    const int j0 = blockIdx.x * 128;
    const float* Ap = g_coefs + (size_t)hn * EN * EN;
    const float* Bp = g_h + (((size_t)(h * TN + 1) * NB) + n) * EN * ON;
    const int tid = threadIdx.x;
    const int tx = tid & 15, ty = tid >> 4;

    float acc[8][8];
#pragma unroll
    for (int i = 0; i < 8; i++)
#pragma unroll
        for (int j = 0; j < 8; j++) acc[i][j] = 0.f;

    for (int k0 = 0; k0 < EN; k0 += 16) {
#pragma unroll
        for (int l = 0; l < 2; l++) {
            int idx = tid * 2 + l;
            int k = idx >> 5;
            int c4 = idx & 31;
            *(float4*)&As[k][c4 * 4] =
                *(const float4*)(Ap + (size_t)(k0 + k) * EN + j0 + c4 * 4);
            *(float4*)&Bs[k][c4 * 4] =
                *(const float4*)(Bp + (size_t)(k0 + k) * ON + c4 * 4);
        }
        __syncthreads();
#pragma unroll
        for (int k = 0; k < 16; k++) {
            float a[8], b[8];
#pragma unroll
            for (int i = 0; i < 8; i++) a[i] = As[k][ty * 8 + i];
#pragma unroll
            for (int j = 0; j < 8; j++) b[j] = Bs[k][tx * 8 + j];
#pragma unroll
            for (int i = 0; i < 8; i++)
#pragma unroll
                for (int j = 0; j < 8; j++) acc[i][j] = fmaf(a[i], b[j], acc[i][j]);
        }
        __syncthreads();
    }

#pragma unroll
    for (int i = 0; i < 8; i++) {
        int j = j0 + ty * 8 + i;
        float* op = out + ((size_t)n * EN + j) * (HN * ON) + h * ON + tx * 8;
#pragma unroll
        for (int j4 = 0; j4 < 2; j4++) {
            float4 v = make_float4(fmaxf(acc[i][j4 * 4 + 0], 0.f),
                                   fmaxf(acc[i][j4 * 4 + 1], 0.f),
                                   fmaxf(acc[i][j4 * 4 + 2], 0.f),
                                   fmaxf(acc[i][j4 * 4 + 3], 0.f));
            *(float4*)(op + j4 * 4) = v;
        }
    }
}

// ====================================================================
extern "C" void kernel_launch(void* const* d_in, const int* in_sizes, int n_in,
                              void* d_out, int out_size)
{
    const float* input_state = (const float*)d_in[0]; // (16,512,1024)
    const int*   adj         = (const int*)d_in[1];   // (16,512,512)
    // d_in[2] entity_mask: unused by reference
    const float* query_vec   = (const float*)d_in[3]; // (16,1024)
    const float* W           = (const float*)d_in[4]; // (8,2,1024,128)
    const float* a_src       = (const float*)d_in[5]; // (8,2,128)
    const float* a_dst       = (const float*)d_in[6]; // (8,2,128)
    const float* qW1         = (const float*)d_in[7]; // (8,2,1024,256)
    const float* qW2         = (const float*)d_in[8]; // (8,2,256,256)
    float* out = (float*)d_out;                       // (16,512,1024)

    // A: h projection GEMM (independent of B)
    gemm_h_kernel<<<dim3(64, 1, HT), 256>>>(input_state, W);
    // B: query gate MLP
    qgate_kernel<<<HT, 256>>>(query_vec, qW1, qW2, a_src, a_dst);
    // C: s1/s2 per-entity dots
    svec_kernel<<<dim3(EN / 8, NB, HT), 256>>>();
    // D: masked scores + softmax -> coefs
    softmax_kernel<<<dim3(EN, NB, HN), 128>>>(adj);
    // E: attention aggregation GEMM + relu + transpose
    gemm_out_kernel<<<dim3(EN / 128, 1, HN * NB), 256>>>(out);
}